// round 8
// baseline (speedup 1.0000x reference)
#include <cuda_runtime.h>
#include <cuda_fp16.h>
#include <math.h>

#define BATCH 2
#define SEQ   4096
#define DMODEL 1024

// Scratch (alloc-free rule: __device__ globals)
__device__ float g_Q[BATCH * SEQ * DMODEL];
__device__ float g_K[BATCH * SEQ * DMODEL];
__device__ float g_V[BATCH * SEQ * DMODEL];
__device__ float g_O[BATCH * SEQ * DMODEL];
__device__ float g_A[(size_t)BATCH * SEQ * SEQ];   // 134 MB
__device__ float g_decay[SEQ];

// ---------------------------------------------------------------------------
__global__ void init_decay_kernel() {
    int i = blockIdx.x * blockDim.x + threadIdx.x;
    if (i < SEQ) g_decay[i] = (float)exp((double)i * log(255.0 / 256.0));
}

__device__ __forceinline__ unsigned pack2(float x, float y) {
    __half2 h = __floats2half2_rn(x, y);
    return *(unsigned*)&h;
}

__device__ __forceinline__ void mma16(float* c, const unsigned* a, const unsigned* b) {
    asm volatile(
        "mma.sync.aligned.m16n8k16.row.col.f32.f16.f16.f32 "
        "{%0,%1,%2,%3}, {%4,%5,%6,%7}, {%8,%9}, {%0,%1,%2,%3};"
        : "+f"(c[0]), "+f"(c[1]), "+f"(c[2]), "+f"(c[3])
        : "r"(a[0]), "r"(a[1]), "r"(a[2]), "r"(a[3]), "r"(b[0]), "r"(b[1]));
}

// ---------------------------------------------------------------------------
// fp16 tensor-core GEMM (fp32 in/out, fp32 accum). Block 128x128xK32,
// 256 threads, 8 warps (2x4), warp tile 64x32, mma.m16n8k16.
// Smem tiles are staged in MMA FRAGMENT ORDER so compute loads are LDS.128 /
// LDS.64, conflict-free. 2-stage double buffer, register staging.
//
// A-frag smem layout (words=half2): [ks2][wmh2][mt4][lane32][r4]
//   word = ks*1024 + wmh*512 + mt*128 + lane*4 + r
// B-frag layout: [ks2][wnh4][nt4][lane32][r2]
//   word = ks*1024 + wnh*256 + nt*64 + lane*2 + r
// TRB:   C = A * B^T  (B given N x K row-major)
// DECAY: C[r][c] *= gamma^(c-r) for c>=r else 0
// M,N multiples of 128; K multiple of 32.
// ---------------------------------------------------------------------------
template<bool TRB, bool DECAY>
__global__ void __launch_bounds__(256, 2) h16gemm(
    const float* __restrict__ Ag, const float* __restrict__ Bg,
    float* __restrict__ Cg,
    int Kdim, int lda, int ldb, int ldc,
    size_t sA, size_t sB, size_t sC)
{
    __shared__ unsigned Af[2][2048];
    __shared__ unsigned Bf[2][2048];

    const float* Ab = Ag + (size_t)blockIdx.z * sA;
    const float* Bb = Bg + (size_t)blockIdx.z * sB;
    float*       Cb = Cg + (size_t)blockIdx.z * sC;

    const int tid   = threadIdx.x;
    const int lane  = tid & 31;
    const int wid   = tid >> 5;
    const int wmh_w = wid & 1;          // warp row half (0..1) -> wm = wmh*64
    const int wnh_w = wid >> 1;         // warp col quarter (0..3) -> wn = wnh*32
    const int g     = lane >> 2;
    const int q     = lane & 3;
    const int row0  = blockIdx.y * 128;
    const int col0  = blockIdx.x * 128;

    float acc[4][4][4];
#pragma unroll
    for (int mt = 0; mt < 4; mt++)
#pragma unroll
        for (int nt = 0; nt < 4; nt++)
#pragma unroll
            for (int i = 0; i < 4; i++) acc[mt][nt][i] = 0.0f;

    // ---- staging thread indices ----
    const int fm  = tid >> 1;           // 0..127  row (A) / n-row (TRB B)
    const int fk0 = (tid & 1) * 4;      // 0 or 4
    const int sa_wmh = fm >> 6, sa_mt = (fm >> 4) & 3;
    const int sa_mh  = (fm >> 3) & 1, sa_g = fm & 7;
    const int sa_t0  = fk0 >> 1;        // 0 or 2
    const int sa_c   = sa_wmh * 512 + sa_mt * 128 + (sa_g * 4 + sa_t0) * 4;
    const float* arow = Ab + (size_t)(row0 + fm) * lda + fk0;

    // TRB B staging (n-major rows)
    const int sb_wnh = fm >> 5, sb_nt = (fm >> 3) & 3;
    const int sbT_c  = sb_wnh * 256 + sb_nt * 64 + (sa_g * 4 + sa_t0) * 2;
    const float* browT = Bb + (size_t)(col0 + fm) * ldb + fk0;

    // NN B staging (k-major rows): thread covers rows 2kp,2kp+1, cols n0 + p*64
    const int kp  = tid >> 4;           // 0..15
    const int n0  = (tid & 15) * 4;     // 0..60
    const int nn_ks = kp >> 3, nn_t = kp & 3, nn_kq = (kp >> 2) & 1;
    const int nn_nt = (n0 >> 3) & 3, nn_g0 = n0 & 7, nn_wb = n0 >> 5;
    const float* brow0 = Bb + (size_t)(2 * kp) * ldb + col0 + n0;

    float4 ra[4], rb[4];

#define LOAD_A(KT) {                                                          \
    const float* s = arow + (KT) * 32;                                        \
    ra[0] = *(const float4*)(s);      ra[1] = *(const float4*)(s + 8);        \
    ra[2] = *(const float4*)(s + 16); ra[3] = *(const float4*)(s + 24); }

#define STS_A(BUF) {                                                          \
    unsigned* A_ = Af[BUF];                                                   \
    _Pragma("unroll")                                                         \
    for (int p = 0; p < 4; p++) {                                             \
        int w = (p >> 1) * 1024 + sa_c + (sa_mh + 2 * (p & 1));               \
        A_[w]     = pack2(ra[p].x, ra[p].y);                                  \
        A_[w + 4] = pack2(ra[p].z, ra[p].w);                                  \
    } }

#define LOAD_B(KT) {                                                          \
    if (TRB) {                                                                \
        const float* s = browT + (KT) * 32;                                   \
        rb[0] = *(const float4*)(s);      rb[1] = *(const float4*)(s + 8);    \
        rb[2] = *(const float4*)(s + 16); rb[3] = *(const float4*)(s + 24);   \
    } else {                                                                  \
        const float* s0 = brow0 + (size_t)(KT) * 32 * ldb;                    \
        const float* s1 = s0 + ldb;                                           \
        rb[0] = *(const float4*)(s0);      rb[1] = *(const float4*)(s1);      \
        rb[2] = *(const float4*)(s0 + 64); rb[3] = *(const float4*)(s1 + 64); \
    } }

#define STS_B(BUF) {                                                          \
    unsigned* B_ = Bf[BUF];                                                   \
    if (TRB) {                                                                \
        _Pragma("unroll")                                                     \
        for (int p = 0; p < 4; p++) {                                         \
            int w = (p >> 1) * 1024 + sbT_c + (p & 1);                        \
            B_[w]     = pack2(rb[p].x, rb[p].y);                              \
            B_[w + 2] = pack2(rb[p].z, rb[p].w);                              \
        }                                                                     \
    } else {                                                                  \
        _Pragma("unroll")                                                     \
        for (int p = 0; p < 2; p++) {                                         \
            int base = nn_ks * 1024 + (nn_wb + p * 2) * 256 + nn_nt * 64      \
                     + nn_t * 2 + nn_kq;                                      \
            float4 e = rb[p * 2], o = rb[p * 2 + 1];                          \
            B_[base + (nn_g0 + 0) * 8] = pack2(e.x, o.x);                     \
            B_[base + (nn_g0 + 1) * 8] = pack2(e.y, o.y);                     \
            B_[base + (nn_g0 + 2) * 8] = pack2(e.z, o.z);                     \
            B_[base + (nn_g0 + 3) * 8] = pack2(e.w, o.w);                     \
        }                                                                     \
    } }

#define COMPUTE(BUF, KS) {                                                    \
    unsigned a_[4][4], b_[4][2];                                              \
    const unsigned* Ap = Af[BUF] + (KS) * 1024 + wmh_w * 512 + lane * 4;      \
    _Pragma("unroll")                                                         \
    for (int mt = 0; mt < 4; mt++)                                            \
        *(uint4*)a_[mt] = *(const uint4*)(Ap + mt * 128);                     \
    const unsigned* Bp = Bf[BUF] + (KS) * 1024 + wnh_w * 256 + lane * 2;      \
    _Pragma("unroll")                                                         \
    for (int nt = 0; nt < 4; nt++) {                                          \
        uint2 v = *(const uint2*)(Bp + nt * 64);                              \
        b_[nt][0] = v.x; b_[nt][1] = v.y;                                     \
    }                                                                         \
    _Pragma("unroll")                                                         \
    for (int mt = 0; mt < 4; mt++)                                            \
        _Pragma("unroll")                                                     \
        for (int nt = 0; nt < 4; nt++)                                        \
            mma16(acc[mt][nt], a_[mt], b_[nt]);                               \
    }

    const int ktiles = Kdim / 32;

    // prologue
    LOAD_A(0); LOAD_B(0);
    STS_A(0);  STS_B(0);
    __syncthreads();

    int p = 0;
    for (int kt = 0; kt < ktiles; kt++) {
        bool more = (kt + 1 < ktiles);
        if (more) LOAD_A(kt + 1);
        COMPUTE(p, 0);
        if (more) LOAD_B(kt + 1);
        COMPUTE(p, 1);
        if (more) {
            STS_A(p ^ 1); STS_B(p ^ 1);
            __syncthreads();
            p ^= 1;
        }
    }

    // ---- epilogue ----
#pragma unroll
    for (int mt = 0; mt < 4; mt++) {
#pragma unroll
        for (int nt = 0; nt < 4; nt++) {
            int r = row0 + wmh_w * 64 + mt * 16 + g;
            int c = col0 + wnh_w * 32 + nt * 8 + 2 * q;
            float v0 = acc[mt][nt][0], v1 = acc[mt][nt][1];
            float v2 = acc[mt][nt][2], v3 = acc[mt][nt][3];
            if (DECAY) {
                int d0 = c - r, d1 = c + 1 - r;
                int d2 = c - (r + 8), d3 = c + 1 - (r + 8);
                v0 = (d0 >= 0) ? v0 * g_decay[d0] : 0.0f;
                v1 = (d1 >= 0) ? v1 * g_decay[d1] : 0.0f;
                v2 = (d2 >= 0) ? v2 * g_decay[d2] : 0.0f;
                v3 = (d3 >= 0) ? v3 * g_decay[d3] : 0.0f;
            }
            *(float2*)(Cb + (size_t)r * ldc + c)       = make_float2(v0, v1);
            *(float2*)(Cb + (size_t)(r + 8) * ldc + c) = make_float2(v2, v3);
        }
    }
#undef LOAD_A
#undef STS_A
#undef LOAD_B
#undef STS_B
#undef COMPUTE
}

// ---------------------------------------------------------------------------
// rope (first 64 channels) + silu. Double-precision trig (t up to 4095 rad).
// ---------------------------------------------------------------------------
template<bool DO_ROPE>
__global__ void act_kernel(float* __restrict__ buf)
{
    int p = blockIdx.x * blockDim.x + threadIdx.x;   // pair index
    if (p >= BATCH * SEQ * (DMODEL / 2)) return;
    float2 v = ((float2*)buf)[p];
    float y0 = v.x, y1 = v.y;
    if (DO_ROPE) {
        int cp = p & (DMODEL / 2 - 1);
        if (cp < 32) {
            int t = (p >> 9) & (SEQ - 1);
            double fr = (double)t * exp((double)cp * -0.28782313662425574);
            float cs = (float)cos(fr);
            float sn = (float)sin(fr);
            float a = v.x, b = v.y;
            y0 = a * cs - b * sn;
            y1 = b * cs + a * sn;
        }
    }
    y0 = y0 / (1.0f + expf(-y0));
    y1 = y1 / (1.0f + expf(-y1));
    ((float2*)buf)[p] = make_float2(y0, y1);
}

// ---------------------------------------------------------------------------
__global__ void groupnorm_kernel(const float* __restrict__ in,
                                 const float* __restrict__ w,
                                 const float* __restrict__ bvec,
                                 float* __restrict__ out)
{
    int row  = blockIdx.x;
    int warp = threadIdx.x >> 5;
    int lane = threadIdx.x & 31;
    const float* r = in  + (size_t)row * DMODEL;
    float*       o = out + (size_t)row * DMODEL;
    for (int g = warp; g < 32; g += 8) {
        int ch = g * 32 + lane;
        float v = r[ch];
        float s = v;
#pragma unroll
        for (int off = 16; off; off >>= 1) s += __shfl_xor_sync(0xffffffffu, s, off);
        float mu = s * (1.0f / 32.0f);
        float dv = v - mu;
        float s2 = dv * dv;
#pragma unroll
        for (int off = 16; off; off >>= 1) s2 += __shfl_xor_sync(0xffffffffu, s2, off);
        float var = s2 * (1.0f / 32.0f);
        float xn = dv * rsqrtf(var + 1e-6f);
        o[ch] = xn * w[ch] + bvec[ch];
    }
}

// ---------------------------------------------------------------------------
extern "C" void kernel_launch(void* const* d_in, const int* in_sizes, int n_in,
                              void* d_out, int out_size)
{
    (void)in_sizes; (void)n_in; (void)out_size;
    const float* X  = (const float*)d_in[0];
    const float* WQ = (const float*)d_in[1];
    const float* WK = (const float*)d_in[2];
    const float* WV = (const float*)d_in[3];
    const float* gw = (const float*)d_in[4];
    const float* gb = (const float*)d_in[5];
    float* out = (float*)d_out;

    float *pQ, *pK, *pV, *pO, *pA;
    cudaGetSymbolAddress((void**)&pQ, g_Q);
    cudaGetSymbolAddress((void**)&pK, g_K);
    cudaGetSymbolAddress((void**)&pV, g_V);
    cudaGetSymbolAddress((void**)&pO, g_O);
    cudaGetSymbolAddress((void**)&pA, g_A);

    init_decay_kernel<<<(SEQ + 255) / 256, 256>>>();

    // Projections: (B*T, 1024) @ (1024, 1024)
    dim3 gProj(DMODEL / 128, (BATCH * SEQ) / 128, 1);
    h16gemm<false, false><<<gProj, 256>>>(X, WQ, pQ, DMODEL, DMODEL, DMODEL, DMODEL, 0, 0, 0);
    h16gemm<false, false><<<gProj, 256>>>(X, WK, pK, DMODEL, DMODEL, DMODEL, DMODEL, 0, 0, 0);
    h16gemm<false, false><<<gProj, 256>>>(X, WV, pV, DMODEL, DMODEL, DMODEL, DMODEL, 0, 0, 0);

    // rope + silu (Q, K), silu (V)
    int pairs = BATCH * SEQ * (DMODEL / 2);
    int ablocks = (pairs + 255) / 256;
    act_kernel<true ><<<ablocks, 256>>>(pQ);
    act_kernel<true ><<<ablocks, 256>>>(pK);
    act_kernel<false><<<ablocks, 256>>>(pV);

    // A = Q K^T with decay epilogue (per batch)
    dim3 gA(SEQ / 128, SEQ / 128, BATCH);
    h16gemm<true, true><<<gA, 256>>>(pQ, pK, pA, DMODEL, DMODEL, DMODEL, SEQ,
                                     (size_t)SEQ * DMODEL, (size_t)SEQ * DMODEL,
                                     (size_t)SEQ * SEQ);

    // O = A V (per batch)
    dim3 gO(DMODEL / 128, SEQ / 128, BATCH);
    h16gemm<false, false><<<gO, 256>>>(pA, pV, pO, SEQ, SEQ, DMODEL, DMODEL,
                                       (size_t)SEQ * SEQ, (size_t)SEQ * DMODEL,
                                       (size_t)SEQ * DMODEL);

    // GroupNorm -> d_out
    groupnorm_kernel<<<BATCH * SEQ, 256>>>(pO, gw, gb, out);
}

// round 9
// speedup vs baseline: 4.0849x; 4.0849x over previous
#include <cuda_runtime.h>
#include <cuda_fp16.h>
#include <math.h>

#define BATCH 2
#define SEQ   4096
#define DMODEL 1024

// Scratch (alloc-free rule: __device__ globals)
__device__ float  g_Q[BATCH * SEQ * DMODEL];
__device__ float  g_K[BATCH * SEQ * DMODEL];
__device__ float  g_V[BATCH * SEQ * DMODEL];
__device__ float  g_O[BATCH * SEQ * DMODEL];
__device__ __half g_Xh[BATCH * SEQ * DMODEL];
__device__ __half g_Wh[3][DMODEL * DMODEL];
__device__ __half g_Qh[BATCH * SEQ * DMODEL];
__device__ __half g_Kh[BATCH * SEQ * DMODEL];
__device__ __half g_Vh[BATCH * SEQ * DMODEL];
__device__ __half g_Ah[(size_t)BATCH * SEQ * SEQ];   // 67 MB
__device__ float  g_decay[SEQ];

// ---------------------------------------------------------------------------
__global__ void init_decay_kernel() {
    int i = blockIdx.x * blockDim.x + threadIdx.x;
    if (i < SEQ) g_decay[i] = (float)exp((double)i * log(255.0 / 256.0));
}

__global__ void cvt_kernel(const float* __restrict__ in, __half* __restrict__ out, int n) {
    int i = blockIdx.x * blockDim.x + threadIdx.x;
    if (i < n) out[i] = __float2half(in[i]);
}

__device__ __forceinline__ unsigned smem_u32(const void* p) {
    return (unsigned)__cvta_generic_to_shared(p);
}

#define CP16(dst, src) \
    asm volatile("cp.async.cg.shared.global [%0], [%1], 16;" :: "r"(dst), "l"(src))
#define CP_COMMIT()  asm volatile("cp.async.commit_group;")
#define CP_WAIT0()   asm volatile("cp.async.wait_group 0;")

#define LDSM4(R0, R1, R2, R3, ADDR) \
    asm volatile("ldmatrix.sync.aligned.m8n8.x4.shared.b16 {%0,%1,%2,%3}, [%4];" \
                 : "=r"(R0), "=r"(R1), "=r"(R2), "=r"(R3) : "r"(ADDR))
#define LDSM4T(R0, R1, R2, R3, ADDR) \
    asm volatile("ldmatrix.sync.aligned.m8n8.x4.trans.shared.b16 {%0,%1,%2,%3}, [%4];" \
                 : "=r"(R0), "=r"(R1), "=r"(R2), "=r"(R3) : "r"(ADDR))

__device__ __forceinline__ void mma16(float* c, const unsigned* a, const unsigned* b) {
    asm volatile(
        "mma.sync.aligned.m16n8k16.row.col.f32.f16.f16.f32 "
        "{%0,%1,%2,%3}, {%4,%5,%6,%7}, {%8,%9}, {%0,%1,%2,%3};"
        : "+f"(c[0]), "+f"(c[1]), "+f"(c[2]), "+f"(c[3])
        : "r"(a[0]), "r"(a[1]), "r"(a[2]), "r"(a[3]), "r"(b[0]), "r"(b[1]));
}

// ---------------------------------------------------------------------------
// fp16 tensor-core GEMM, cp.async + ldmatrix + XOR swizzle.
// Block 128x128, K-tile 64, 256 threads, 8 warps (2x4), warp tile 64x32.
//
// Smem (bytes, per stage of 32768): A tile [row 0..127][128B: 64 halves of k],
// chunk c (16B) stored at phys = c ^ (row&7). B at +16384:
//   BMODE==1 (TRB, B is NxK): same layout as A (row=n).
//   BMODE==0 (NN,  B is KxN): two subtiles [nh][krow 0..63][128B: 64 halves
//   of n], phys = c ^ (krow&7); consumed with ldmatrix.trans.
// OMODE: 0 = fp32 out; 1 = fp16 out with anti-causal decay epilogue
//        (and tile skip: col0 < row0 fully zero, never written).
// TRIL:  A operand upper-triangular -> K loop starts at row0.
// ---------------------------------------------------------------------------
template<int BMODE, int OMODE, bool TRIL>
__global__ void __launch_bounds__(256) hgemm(
    const __half* __restrict__ Ag, const __half* __restrict__ Bg,
    void* __restrict__ Cv,
    int Kdim, int lda, int ldb, int ldc,
    size_t sA, size_t sB, size_t sC)
{
    extern __shared__ __half S[];

    const int row0 = blockIdx.y * 128;
    const int col0 = blockIdx.x * 128;
    if (OMODE == 1 && col0 < row0) return;   // fully-zero tile, never read

    const __half* Aop = Ag + (size_t)blockIdx.z * sA;
    const __half* Bop = Bg + (size_t)blockIdx.z * sB;

    const int tid  = threadIdx.x;
    const int lane = tid & 31;
    const int wid  = tid >> 5;
    const int wmh  = wid & 1;           // warp m-half (0..1) -> m off 64
    const int wnh  = wid >> 1;          // warp n-quarter (0..3) -> n off 32
    const int g    = lane >> 2;
    const int q    = lane & 3;
    const int rl   = lane & 7;
    const int hk   = (lane >> 3) & 1;
    const int hn   = (lane >> 4) & 1;

    const unsigned sbase = smem_u32(S);

    // ---- cp.async staging indices ----
    const int rowA = tid >> 1;          // 0..127
    const int cb   = (tid & 1) * 4;     // chunk base 0/4
    const int ar7  = rowA & 7;
    // NN B staging
    const int krow = tid & 63;
    const int cg   = tid >> 6;          // 0..3
    const int kr7  = krow & 7;

    // ---- ldmatrix per-lane bases (bytes within a stage) ----
    const int aRow  = wmh * 64 + rl + hk * 8;            // A frag row (mt=0)
    const int bTrow = wnh * 32 + rl + hn * 8;            // TRB frag row (pair=0)
    // NN trans bases per pair
    int bNN[2];
#pragma unroll
    for (int pair = 0; pair < 2; pair++) {
        int nb   = wnh * 32 + pair * 16 + hn * 8;
        int nh   = nb >> 6;
        int phys = ((nb >> 3) & 7) ^ rl;
        bNN[pair] = 16384 + nh * 8192 + (rl + hk * 8) * 128 + phys * 16;
    }

    float acc[4][4][4];
#pragma unroll
    for (int mt = 0; mt < 4; mt++)
#pragma unroll
        for (int nt = 0; nt < 4; nt++)
#pragma unroll
            for (int i = 0; i < 4; i++) acc[mt][nt][i] = 0.0f;

#define ISSUE(KT, STG) {                                                       \
    unsigned sb = sbase + (STG) * 32768;                                       \
    const __half* asrc = Aop + (size_t)(row0 + rowA) * lda + (KT) * 64 + cb * 8; \
    _Pragma("unroll")                                                          \
    for (int cc = 0; cc < 4; cc++)                                             \
        CP16(sb + rowA * 128 + (((cb + cc) ^ ar7) * 16), asrc + cc * 8);       \
    if (BMODE == 1) {                                                          \
        const __half* bsrc = Bop + (size_t)(col0 + rowA) * ldb + (KT) * 64 + cb * 8; \
        _Pragma("unroll")                                                      \
        for (int cc = 0; cc < 4; cc++)                                         \
            CP16(sb + 16384 + rowA * 128 + (((cb + cc) ^ ar7) * 16), bsrc + cc * 8); \
    } else {                                                                   \
        const __half* bsrc = Bop + (size_t)((KT) * 64 + krow) * ldb + col0;    \
        _Pragma("unroll")                                                      \
        for (int cc = 0; cc < 4; cc++) {                                       \
            int chunk = cg + cc * 4;                                           \
            CP16(sb + 16384 + (chunk >> 3) * 8192 + krow * 128                 \
                    + (((chunk & 7) ^ kr7) * 16), bsrc + chunk * 8);           \
        }                                                                      \
    }                                                                          \
    CP_COMMIT(); }

#define COMPUTE(STG) {                                                         \
    unsigned pb = sbase + (STG) * 32768;                                       \
    _Pragma("unroll")                                                          \
    for (int ksb = 0; ksb < 4; ksb++) {                                        \
        unsigned aF[4][4], bF[4][2];                                           \
        unsigned physA = (unsigned)((2 * ksb + hn) ^ rl);                      \
        unsigned aoff  = pb + aRow * 128 + physA * 16;                         \
        _Pragma("unroll")                                                      \
        for (int mt = 0; mt < 4; mt++)                                         \
            LDSM4(aF[mt][0], aF[mt][1], aF[mt][2], aF[mt][3], aoff + mt * 2048); \
        if (BMODE == 1) {                                                      \
            unsigned physB = (unsigned)((2 * ksb + hk) ^ rl);                  \
            _Pragma("unroll")                                                  \
            for (int pair = 0; pair < 2; pair++) {                             \
                unsigned ba = pb + 16384 + (bTrow + pair * 16) * 128 + physB * 16; \
                LDSM4(bF[pair*2][0], bF[pair*2][1],                            \
                      bF[pair*2+1][0], bF[pair*2+1][1], ba);                   \
            }                                                                  \
        } else {                                                               \
            _Pragma("unroll")                                                  \
            for (int pair = 0; pair < 2; pair++) {                             \
                unsigned ba = pb + bNN[pair] + ksb * 2048;                     \
                LDSM4T(bF[pair*2][0], bF[pair*2][1],                           \
                       bF[pair*2+1][0], bF[pair*2+1][1], ba);                  \
            }                                                                  \
        }                                                                      \
        _Pragma("unroll")                                                      \
        for (int mt = 0; mt < 4; mt++)                                         \
            _Pragma("unroll")                                                  \
            for (int nt = 0; nt < 4; nt++)                                     \
                mma16(acc[mt][nt], aF[mt], bF[nt]);                            \
    } }

    const int ktiles = Kdim / 64;
    const int kt0    = TRIL ? (row0 >> 6) : 0;

    ISSUE(kt0, 0);
    int p = 0;
    for (int kt = kt0; kt < ktiles; kt++) {
        CP_WAIT0();
        __syncthreads();                 // stage p ready; prior compute done
        if (kt + 1 < ktiles) ISSUE(kt + 1, p ^ 1);
        COMPUTE(p);
        p ^= 1;
    }

    // ---- epilogue ----
    float*  Cf = (float*)Cv  + (OMODE == 0 ? (size_t)blockIdx.z * sC : 0);
    __half* Ch = (__half*)Cv + (OMODE == 1 ? (size_t)blockIdx.z * sC : 0);
#pragma unroll
    for (int mt = 0; mt < 4; mt++) {
#pragma unroll
        for (int nt = 0; nt < 4; nt++) {
            int r = row0 + wmh * 64 + mt * 16 + g;
            int c = col0 + wnh * 32 + nt * 8 + 2 * q;
            float v0 = acc[mt][nt][0], v1 = acc[mt][nt][1];
            float v2 = acc[mt][nt][2], v3 = acc[mt][nt][3];
            if (OMODE == 1) {
                int d0 = c - r,       d1 = c + 1 - r;
                int d2 = c - (r + 8), d3 = c + 1 - (r + 8);
                v0 = (d0 >= 0) ? v0 * g_decay[d0] : 0.0f;
                v1 = (d1 >= 0) ? v1 * g_decay[d1] : 0.0f;
                v2 = (d2 >= 0) ? v2 * g_decay[d2] : 0.0f;
                v3 = (d3 >= 0) ? v3 * g_decay[d3] : 0.0f;
                *(__half2*)(Ch + (size_t)r * ldc + c)       = __floats2half2_rn(v0, v1);
                *(__half2*)(Ch + (size_t)(r + 8) * ldc + c) = __floats2half2_rn(v2, v3);
            } else {
                *(float2*)(Cf + (size_t)r * ldc + c)       = make_float2(v0, v1);
                *(float2*)(Cf + (size_t)(r + 8) * ldc + c) = make_float2(v2, v3);
            }
        }
    }
#undef ISSUE
#undef COMPUTE
}

// ---------------------------------------------------------------------------
// rope (first 64 channels) + silu: fp32 in -> fp16 out.
// Double-precision trig (t up to 4095 rad; float range reduction too lossy).
// ---------------------------------------------------------------------------
template<bool DO_ROPE>
__global__ void act_kernel(const float* __restrict__ in, __half* __restrict__ out)
{
    int p = blockIdx.x * blockDim.x + threadIdx.x;   // pair index
    if (p >= BATCH * SEQ * (DMODEL / 2)) return;
    float2 v = ((const float2*)in)[p];
    float y0 = v.x, y1 = v.y;
    if (DO_ROPE) {
        int cp = p & (DMODEL / 2 - 1);
        if (cp < 32) {
            int t = (p >> 9) & (SEQ - 1);
            double fr = (double)t * exp((double)cp * -0.28782313662425574);
            float cs = (float)cos(fr);
            float sn = (float)sin(fr);
            float a = v.x, b = v.y;
            y0 = a * cs - b * sn;
            y1 = b * cs + a * sn;
        }
    }
    y0 = y0 / (1.0f + expf(-y0));
    y1 = y1 / (1.0f + expf(-y1));
    ((__half2*)out)[p] = __floats2half2_rn(y0, y1);
}

// ---------------------------------------------------------------------------
__global__ void groupnorm_kernel(const float* __restrict__ in,
                                 const float* __restrict__ w,
                                 const float* __restrict__ bvec,
                                 float* __restrict__ out)
{
    int row  = blockIdx.x;
    int warp = threadIdx.x >> 5;
    int lane = threadIdx.x & 31;
    const float* r = in  + (size_t)row * DMODEL;
    float*       o = out + (size_t)row * DMODEL;
    for (int g = warp; g < 32; g += 8) {
        int ch = g * 32 + lane;
        float v = r[ch];
        float s = v;
#pragma unroll
        for (int off = 16; off; off >>= 1) s += __shfl_xor_sync(0xffffffffu, s, off);
        float mu = s * (1.0f / 32.0f);
        float dv = v - mu;
        float s2 = dv * dv;
#pragma unroll
        for (int off = 16; off; off >>= 1) s2 += __shfl_xor_sync(0xffffffffu, s2, off);
        float var = s2 * (1.0f / 32.0f);
        float xn = dv * rsqrtf(var + 1e-6f);
        o[ch] = xn * w[ch] + bvec[ch];
    }
}

// ---------------------------------------------------------------------------
extern "C" void kernel_launch(void* const* d_in, const int* in_sizes, int n_in,
                              void* d_out, int out_size)
{
    (void)in_sizes; (void)n_in; (void)out_size;
    const float* X  = (const float*)d_in[0];
    const float* WQ = (const float*)d_in[1];
    const float* WK = (const float*)d_in[2];
    const float* WV = (const float*)d_in[3];
    const float* gw = (const float*)d_in[4];
    const float* gb = (const float*)d_in[5];
    float* out = (float*)d_out;

    float *pQ, *pK, *pV, *pO;
    __half *pXh, *pWh, *pQh, *pKh, *pVh, *pAh;
    cudaGetSymbolAddress((void**)&pQ,  g_Q);
    cudaGetSymbolAddress((void**)&pK,  g_K);
    cudaGetSymbolAddress((void**)&pV,  g_V);
    cudaGetSymbolAddress((void**)&pO,  g_O);
    cudaGetSymbolAddress((void**)&pXh, g_Xh);
    cudaGetSymbolAddress((void**)&pWh, g_Wh);
    cudaGetSymbolAddress((void**)&pQh, g_Qh);
    cudaGetSymbolAddress((void**)&pKh, g_Kh);
    cudaGetSymbolAddress((void**)&pVh, g_Vh);
    cudaGetSymbolAddress((void**)&pAh, g_Ah);

    cudaFuncSetAttribute(hgemm<0,0,false>, cudaFuncAttributeMaxDynamicSharedMemorySize, 65536);
    cudaFuncSetAttribute(hgemm<1,1,false>, cudaFuncAttributeMaxDynamicSharedMemorySize, 65536);
    cudaFuncSetAttribute(hgemm<0,0,true >, cudaFuncAttributeMaxDynamicSharedMemorySize, 65536);

    init_decay_kernel<<<(SEQ + 255) / 256, 256>>>();

    // fp32 -> fp16 operand conversion
    int nx = BATCH * SEQ * DMODEL, nw = DMODEL * DMODEL;
    cvt_kernel<<<(nx + 255) / 256, 256>>>(X,  pXh, nx);
    cvt_kernel<<<(nw + 255) / 256, 256>>>(WQ, pWh + 0 * (size_t)nw, nw);
    cvt_kernel<<<(nw + 255) / 256, 256>>>(WK, pWh + 1 * (size_t)nw, nw);
    cvt_kernel<<<(nw + 255) / 256, 256>>>(WV, pWh + 2 * (size_t)nw, nw);

    // Projections: (B*T,1024) @ (1024,1024) -> fp32
    dim3 gProj(DMODEL / 128, (BATCH * SEQ) / 128, 1);
    hgemm<0,0,false><<<gProj, 256, 65536>>>(pXh, pWh + 0 * (size_t)nw, pQ,
                                            DMODEL, DMODEL, DMODEL, DMODEL, 0, 0, 0);
    hgemm<0,0,false><<<gProj, 256, 65536>>>(pXh, pWh + 1 * (size_t)nw, pK,
                                            DMODEL, DMODEL, DMODEL, DMODEL, 0, 0, 0);
    hgemm<0,0,false><<<gProj, 256, 65536>>>(pXh, pWh + 2 * (size_t)nw, pV,
                                            DMODEL, DMODEL, DMODEL, DMODEL, 0, 0, 0);

    // rope + silu (Q, K), silu (V): fp32 -> fp16
    int pairs = BATCH * SEQ * (DMODEL / 2);
    int ablocks = (pairs + 255) / 256;
    act_kernel<true ><<<ablocks, 256>>>(pQ, pQh);
    act_kernel<true ><<<ablocks, 256>>>(pK, pKh);
    act_kernel<false><<<ablocks, 256>>>(pV, pVh);

    // A = Q K^T (TRB) with decay epilogue -> fp16; lower tiles skipped
    dim3 gA(SEQ / 128, SEQ / 128, BATCH);
    hgemm<1,1,false><<<gA, 256, 65536>>>(pQh, pKh, pAh, DMODEL, DMODEL, DMODEL, SEQ,
                                         (size_t)SEQ * DMODEL, (size_t)SEQ * DMODEL,
                                         (size_t)SEQ * SEQ);

    // O = A V (NN, A upper-triangular: K loop starts at row0) -> fp32
    dim3 gO(DMODEL / 128, SEQ / 128, BATCH);
    hgemm<0,0,true><<<gO, 256, 65536>>>(pAh, pVh, pO, SEQ, SEQ, DMODEL, DMODEL,
                                        (size_t)SEQ * SEQ, (size_t)SEQ * DMODEL,
                                        (size_t)SEQ * DMODEL);

    // GroupNorm -> d_out
    groupnorm_kernel<<<BATCH * SEQ, 256>>>(pO, gw, gb, out);
}

// round 10
// speedup vs baseline: 4.5564x; 1.1154x over previous
#include <cuda_runtime.h>
#include <cuda_fp16.h>
#include <math.h>

#define BATCH 2
#define SEQ   4096
#define DMODEL 1024

// Scratch (alloc-free rule: __device__ globals)
__device__ __half g_Xh[BATCH * SEQ * DMODEL];
__device__ __half g_Wh[3][DMODEL * DMODEL];
__device__ __half g_Qh[BATCH * SEQ * DMODEL];
__device__ __half g_Kh[BATCH * SEQ * DMODEL];
__device__ __half g_Vh[BATCH * SEQ * DMODEL];
__device__ __half g_Ah[(size_t)BATCH * SEQ * SEQ];   // 67 MB
__device__ float  g_decay[SEQ];
__device__ float2 g_rope[SEQ * 32];                  // (cos, sin) per (t, pair)

// ---------------------------------------------------------------------------
__global__ void init_decay_kernel() {
    int i = blockIdx.x * blockDim.x + threadIdx.x;
    if (i < SEQ) g_decay[i] = (float)exp((double)i * log(255.0 / 256.0));
}

__global__ void init_rope_kernel() {
    int i = blockIdx.x * blockDim.x + threadIdx.x;   // t*32 + cp
    if (i < SEQ * 32) {
        int t = i >> 5, cp = i & 31;
        // inv_freq = 10000^(-cp/32); ln(10000)/32 = 0.28782313662425574
        double fr = (double)t * exp((double)cp * -0.28782313662425574);
        g_rope[i] = make_float2((float)cos(fr), (float)sin(fr));
    }
}

__global__ void cvt_kernel(const float* __restrict__ in, __half* __restrict__ out, int n) {
    int i = blockIdx.x * blockDim.x + threadIdx.x;
    if (i < n) out[i] = __float2half(in[i]);
}

__device__ __forceinline__ unsigned smem_u32(const void* p) {
    return (unsigned)__cvta_generic_to_shared(p);
}

#define CP16(dst, src) \
    asm volatile("cp.async.cg.shared.global [%0], [%1], 16;" :: "r"(dst), "l"(src))
#define CP_COMMIT()  asm volatile("cp.async.commit_group;")
#define CP_WAIT0()   asm volatile("cp.async.wait_group 0;")

#define LDSM4(R0, R1, R2, R3, ADDR) \
    asm volatile("ldmatrix.sync.aligned.m8n8.x4.shared.b16 {%0,%1,%2,%3}, [%4];" \
                 : "=r"(R0), "=r"(R1), "=r"(R2), "=r"(R3) : "r"(ADDR))
#define LDSM4T(R0, R1, R2, R3, ADDR) \
    asm volatile("ldmatrix.sync.aligned.m8n8.x4.trans.shared.b16 {%0,%1,%2,%3}, [%4];" \
                 : "=r"(R0), "=r"(R1), "=r"(R2), "=r"(R3) : "r"(ADDR))

__device__ __forceinline__ void mma16(float* c, const unsigned* a, const unsigned* b) {
    asm volatile(
        "mma.sync.aligned.m16n8k16.row.col.f32.f16.f16.f32 "
        "{%0,%1,%2,%3}, {%4,%5,%6,%7}, {%8,%9}, {%0,%1,%2,%3};"
        : "+f"(c[0]), "+f"(c[1]), "+f"(c[2]), "+f"(c[3])
        : "r"(a[0]), "r"(a[1]), "r"(a[2]), "r"(a[3]), "r"(b[0]), "r"(b[1]));
}

__device__ __forceinline__ float silu(float x) {
    return x / (1.0f + expf(-x));
}

// ---------------------------------------------------------------------------
// fp16 tensor-core GEMM, cp.async + ldmatrix + XOR swizzle.
// Block 128x128, K-tile 64, 256 threads, 8 warps (2x4), warp tile 64x32.
//
// Smem per 32KB stage: A tile [row][128B of k], chunk c at phys = c ^ (row&7).
// B at +16384:  BMODE==1 (TRB, NxK): same layout (row=n).
//               BMODE==0 (NN, KxN): 2 subtiles [nh][krow][128B of n],
//               consumed via ldmatrix.trans.
// OMODE: 0 fp32 out
//        1 fp16 out + anti-causal decay (+ tile skip col0<row0)
//        2 fp16 out + rope + silu      (Q/K projection)
//        3 fp16 out + silu             (V projection)
//        4 fp32 out + fused GroupNorm  (AV epilogue; group == warp n-extent)
// TRIL:  A operand upper-triangular -> K loop starts at row0.
// ---------------------------------------------------------------------------
template<int BMODE, int OMODE, bool TRIL>
__global__ void __launch_bounds__(256, 2) hgemm(
    const __half* __restrict__ Ag, const __half* __restrict__ Bg,
    void* __restrict__ Cv,
    const float* __restrict__ gwp, const float* __restrict__ gbp,
    int Kdim, int lda, int ldb, int ldc,
    size_t sA, size_t sB, size_t sC)
{
    extern __shared__ __half S[];

    const int row0 = blockIdx.y * 128;
    const int col0 = blockIdx.x * 128;
    if (OMODE == 1 && col0 < row0) return;   // fully-zero tile, never read

    const __half* Aop = Ag + (size_t)blockIdx.z * sA;
    const __half* Bop = Bg + (size_t)blockIdx.z * sB;

    const int tid  = threadIdx.x;
    const int lane = tid & 31;
    const int wid  = tid >> 5;
    const int wmh  = wid & 1;           // warp m-half -> m off 64
    const int wnh  = wid >> 1;          // warp n-quarter -> n off 32
    const int g    = lane >> 2;
    const int q    = lane & 3;
    const int rl   = lane & 7;
    const int hk   = (lane >> 3) & 1;
    const int hn   = (lane >> 4) & 1;

    const unsigned sbase = smem_u32(S);

    // ---- cp.async staging indices ----
    const int rowA = tid >> 1;          // 0..127
    const int cb   = (tid & 1) * 4;     // chunk base 0/4
    const int ar7  = rowA & 7;
    const int krow = tid & 63;          // NN B staging
    const int cg   = tid >> 6;          // 0..3
    const int kr7  = krow & 7;

    // ---- ldmatrix per-lane bases ----
    const int aRow  = wmh * 64 + rl + hk * 8;
    const int bTrow = wnh * 32 + rl + hn * 8;
    int bNN[2];
#pragma unroll
    for (int pair = 0; pair < 2; pair++) {
        int nb   = wnh * 32 + pair * 16 + hn * 8;
        int nh   = nb >> 6;
        int phys = ((nb >> 3) & 7) ^ rl;
        bNN[pair] = 16384 + nh * 8192 + (rl + hk * 8) * 128 + phys * 16;
    }

    float acc[4][4][4];
#pragma unroll
    for (int mt = 0; mt < 4; mt++)
#pragma unroll
        for (int nt = 0; nt < 4; nt++)
#pragma unroll
            for (int i = 0; i < 4; i++) acc[mt][nt][i] = 0.0f;

#define ISSUE(KT, STG) {                                                       \
    unsigned sb = sbase + (STG) * 32768;                                       \
    const __half* asrc = Aop + (size_t)(row0 + rowA) * lda + (KT) * 64 + cb * 8; \
    _Pragma("unroll")                                                          \
    for (int cc = 0; cc < 4; cc++)                                             \
        CP16(sb + rowA * 128 + (((cb + cc) ^ ar7) * 16), asrc + cc * 8);       \
    if (BMODE == 1) {                                                          \
        const __half* bsrc = Bop + (size_t)(col0 + rowA) * ldb + (KT) * 64 + cb * 8; \
        _Pragma("unroll")                                                      \
        for (int cc = 0; cc < 4; cc++)                                         \
            CP16(sb + 16384 + rowA * 128 + (((cb + cc) ^ ar7) * 16), bsrc + cc * 8); \
    } else {                                                                   \
        const __half* bsrc = Bop + (size_t)((KT) * 64 + krow) * ldb + col0;    \
        _Pragma("unroll")                                                      \
        for (int cc = 0; cc < 4; cc++) {                                       \
            int chunk = cg + cc * 4;                                           \
            CP16(sb + 16384 + (chunk >> 3) * 8192 + krow * 128                 \
                    + (((chunk & 7) ^ kr7) * 16), bsrc + chunk * 8);           \
        }                                                                      \
    }                                                                          \
    CP_COMMIT(); }

#define COMPUTE(STG) {                                                         \
    unsigned pb = sbase + (STG) * 32768;                                       \
    _Pragma("unroll")                                                          \
    for (int ksb = 0; ksb < 4; ksb++) {                                        \
        unsigned aF[4][4], bF[4][2];                                           \
        unsigned physA = (unsigned)((2 * ksb + hn) ^ rl);                      \
        unsigned aoff  = pb + aRow * 128 + physA * 16;                         \
        _Pragma("unroll")                                                      \
        for (int mt = 0; mt < 4; mt++)                                         \
            LDSM4(aF[mt][0], aF[mt][1], aF[mt][2], aF[mt][3], aoff + mt * 2048); \
        if (BMODE == 1) {                                                      \
            unsigned physB = (unsigned)((2 * ksb + hk) ^ rl);                  \
            _Pragma("unroll")                                                  \
            for (int pair = 0; pair < 2; pair++) {                             \
                unsigned ba = pb + 16384 + (bTrow + pair * 16) * 128 + physB * 16; \
                LDSM4(bF[pair*2][0], bF[pair*2][1],                            \
                      bF[pair*2+1][0], bF[pair*2+1][1], ba);                   \
            }                                                                  \
        } else {                                                               \
            _Pragma("unroll")                                                  \
            for (int pair = 0; pair < 2; pair++) {                             \
                unsigned ba = pb + bNN[pair] + ksb * 2048;                     \
                LDSM4T(bF[pair*2][0], bF[pair*2][1],                           \
                       bF[pair*2+1][0], bF[pair*2+1][1], ba);                  \
            }                                                                  \
        }                                                                      \
        _Pragma("unroll")                                                      \
        for (int mt = 0; mt < 4; mt++)                                         \
            _Pragma("unroll")                                                  \
            for (int nt = 0; nt < 4; nt++)                                     \
                mma16(acc[mt][nt], aF[mt], bF[nt]);                            \
    } }

    const int ktiles = Kdim / 64;
    const int kt0    = TRIL ? (row0 >> 6) : 0;

    ISSUE(kt0, 0);
    int p = 0;
    for (int kt = kt0; kt < ktiles; kt++) {
        CP_WAIT0();
        __syncthreads();
        if (kt + 1 < ktiles) ISSUE(kt + 1, p ^ 1);
        COMPUTE(p);
        p ^= 1;
    }

    // ======================= epilogues =======================
    if (OMODE == 4) {
        // fused GroupNorm: one group (32 ch) == this warp's n-extent.
        float* Cf = (float*)Cv + (size_t)blockIdx.z * sC;
#pragma unroll
        for (int mt = 0; mt < 4; mt++) {
#pragma unroll
            for (int h = 0; h < 2; h++) {
                float vv[8];
                float s1 = 0.0f;
#pragma unroll
                for (int nt = 0; nt < 4; nt++) {
                    vv[nt * 2]     = acc[mt][nt][2 * h];
                    vv[nt * 2 + 1] = acc[mt][nt][2 * h + 1];
                    s1 += vv[nt * 2] + vv[nt * 2 + 1];
                }
                s1 += __shfl_xor_sync(0xffffffffu, s1, 1);
                s1 += __shfl_xor_sync(0xffffffffu, s1, 2);
                float mu = s1 * (1.0f / 32.0f);
                float s2 = 0.0f;
#pragma unroll
                for (int i = 0; i < 8; i++) {
                    float d = vv[i] - mu;
                    s2 += d * d;
                }
                s2 += __shfl_xor_sync(0xffffffffu, s2, 1);
                s2 += __shfl_xor_sync(0xffffffffu, s2, 2);
                float rs = rsqrtf(s2 * (1.0f / 32.0f) + 1e-6f);
                int r = row0 + wmh * 64 + mt * 16 + g + h * 8;
#pragma unroll
                for (int nt = 0; nt < 4; nt++) {
                    int c = col0 + wnh * 32 + nt * 8 + 2 * q;
                    float o0 = (vv[nt * 2]     - mu) * rs * gwp[c]     + gbp[c];
                    float o1 = (vv[nt * 2 + 1] - mu) * rs * gwp[c + 1] + gbp[c + 1];
                    *(float2*)(Cf + (size_t)r * ldc + c) = make_float2(o0, o1);
                }
            }
        }
    } else {
        float*  Cf = (float*)Cv  + (OMODE == 0 ? (size_t)blockIdx.z * sC : 0);
        __half* Ch = (__half*)Cv + (OMODE != 0 ? (size_t)blockIdx.z * sC : 0);
#pragma unroll
        for (int mt = 0; mt < 4; mt++) {
#pragma unroll
            for (int nt = 0; nt < 4; nt++) {
                int r = row0 + wmh * 64 + mt * 16 + g;
                int c = col0 + wnh * 32 + nt * 8 + 2 * q;
                float v0 = acc[mt][nt][0], v1 = acc[mt][nt][1];
                float v2 = acc[mt][nt][2], v3 = acc[mt][nt][3];
                if (OMODE == 1) {
                    int d0 = c - r,       d1 = c + 1 - r;
                    int d2 = c - (r + 8), d3 = c + 1 - (r + 8);
                    v0 = (d0 >= 0) ? v0 * g_decay[d0] : 0.0f;
                    v1 = (d1 >= 0) ? v1 * g_decay[d1] : 0.0f;
                    v2 = (d2 >= 0) ? v2 * g_decay[d2] : 0.0f;
                    v3 = (d3 >= 0) ? v3 * g_decay[d3] : 0.0f;
                } else if (OMODE == 2 || OMODE == 3) {
                    if (OMODE == 2 && c < 64) {
                        int cp = c >> 1;
                        float2 cs0 = g_rope[((r)     & (SEQ - 1)) * 32 + cp];
                        float2 cs1 = g_rope[((r + 8) & (SEQ - 1)) * 32 + cp];
                        float a0 = v0, b0 = v1, a1 = v2, b1 = v3;
                        v0 = a0 * cs0.x - b0 * cs0.y;
                        v1 = b0 * cs0.x + a0 * cs0.y;
                        v2 = a1 * cs1.x - b1 * cs1.y;
                        v3 = b1 * cs1.x + a1 * cs1.y;
                    }
                    v0 = silu(v0); v1 = silu(v1);
                    v2 = silu(v2); v3 = silu(v3);
                }
                if (OMODE == 0) {
                    *(float2*)(Cf + (size_t)r * ldc + c)       = make_float2(v0, v1);
                    *(float2*)(Cf + (size_t)(r + 8) * ldc + c) = make_float2(v2, v3);
                } else {
                    *(__half2*)(Ch + (size_t)r * ldc + c)       = __floats2half2_rn(v0, v1);
                    *(__half2*)(Ch + (size_t)(r + 8) * ldc + c) = __floats2half2_rn(v2, v3);
                }
            }
        }
    }
#undef ISSUE
#undef COMPUTE
}

// ---------------------------------------------------------------------------
extern "C" void kernel_launch(void* const* d_in, const int* in_sizes, int n_in,
                              void* d_out, int out_size)
{
    (void)in_sizes; (void)n_in; (void)out_size;
    const float* X  = (const float*)d_in[0];
    const float* WQ = (const float*)d_in[1];
    const float* WK = (const float*)d_in[2];
    const float* WV = (const float*)d_in[3];
    const float* gw = (const float*)d_in[4];
    const float* gb = (const float*)d_in[5];
    float* out = (float*)d_out;

    __half *pXh, *pWh, *pQh, *pKh, *pVh, *pAh;
    cudaGetSymbolAddress((void**)&pXh, g_Xh);
    cudaGetSymbolAddress((void**)&pWh, g_Wh);
    cudaGetSymbolAddress((void**)&pQh, g_Qh);
    cudaGetSymbolAddress((void**)&pKh, g_Kh);
    cudaGetSymbolAddress((void**)&pVh, g_Vh);
    cudaGetSymbolAddress((void**)&pAh, g_Ah);

    cudaFuncSetAttribute(hgemm<0,2,false>, cudaFuncAttributeMaxDynamicSharedMemorySize, 65536);
    cudaFuncSetAttribute(hgemm<0,3,false>, cudaFuncAttributeMaxDynamicSharedMemorySize, 65536);
    cudaFuncSetAttribute(hgemm<1,1,false>, cudaFuncAttributeMaxDynamicSharedMemorySize, 65536);
    cudaFuncSetAttribute(hgemm<0,4,true >, cudaFuncAttributeMaxDynamicSharedMemorySize, 65536);

    init_decay_kernel<<<(SEQ + 255) / 256, 256>>>();
    init_rope_kernel<<<(SEQ * 32 + 255) / 256, 256>>>();

    // fp32 -> fp16 operand conversion
    int nx = BATCH * SEQ * DMODEL, nw = DMODEL * DMODEL;
    cvt_kernel<<<(nx + 255) / 256, 256>>>(X,  pXh, nx);
    cvt_kernel<<<(nw + 255) / 256, 256>>>(WQ, pWh + 0 * (size_t)nw, nw);
    cvt_kernel<<<(nw + 255) / 256, 256>>>(WK, pWh + 1 * (size_t)nw, nw);
    cvt_kernel<<<(nw + 255) / 256, 256>>>(WV, pWh + 2 * (size_t)nw, nw);

    // Projections with fused rope+silu (Q,K) / silu (V) -> fp16
    dim3 gProj(DMODEL / 128, (BATCH * SEQ) / 128, 1);
    hgemm<0,2,false><<<gProj, 256, 65536>>>(pXh, pWh + 0 * (size_t)nw, pQh, 0, 0,
                                            DMODEL, DMODEL, DMODEL, DMODEL, 0, 0, 0);
    hgemm<0,2,false><<<gProj, 256, 65536>>>(pXh, pWh + 1 * (size_t)nw, pKh, 0, 0,
                                            DMODEL, DMODEL, DMODEL, DMODEL, 0, 0, 0);
    hgemm<0,3,false><<<gProj, 256, 65536>>>(pXh, pWh + 2 * (size_t)nw, pVh, 0, 0,
                                            DMODEL, DMODEL, DMODEL, DMODEL, 0, 0, 0);

    // A = Q K^T (TRB) with decay epilogue -> fp16; lower tiles skipped
    dim3 gA(SEQ / 128, SEQ / 128, BATCH);
    hgemm<1,1,false><<<gA, 256, 65536>>>(pQh, pKh, pAh, 0, 0,
                                         DMODEL, DMODEL, DMODEL, SEQ,
                                         (size_t)SEQ * DMODEL, (size_t)SEQ * DMODEL,
                                         (size_t)SEQ * SEQ);

    // O = A V (NN, TRIL) with fused GroupNorm -> d_out (fp32)
    dim3 gO(DMODEL / 128, SEQ / 128, BATCH);
    hgemm<0,4,true><<<gO, 256, 65536>>>(pAh, pVh, out, gw, gb,
                                        SEQ, SEQ, DMODEL, DMODEL,
                                        (size_t)SEQ * SEQ, (size_t)SEQ * DMODEL,
                                        (size_t)SEQ * DMODEL);
}